// round 16
// baseline (speedup 1.0000x reference)
#include <cuda_runtime.h>
#include <cuda_bf16.h>
#include <mma.h>
#include <cstdint>

using namespace nvcuda;

// ---------------------------------------------------------------------------
// Model_57183194578962 — fused neighbor-attention + cosine loss
// B=512, N=100, E=512, D_MODEL=1024, H=8, DEPTH=128, VOCAB=50000
//
// Round 15: q_post/att_post fused into GEMM epilogues (EPI template mode);
// attn_fused phase C (xbar) vectorized to float4 smem loads.
// ---------------------------------------------------------------------------

#define Bsz 512
#define Nn  100
#define Ee  512
#define DM  1024
#define Hh  8
#define DEPTH 128

// ------------------------- static scratch ----------------------------------
__device__ float g_Q [2 * Bsz * DM];
__device__ float g_U [16 * Bsz * Ee];
__device__ float g_r4[16 * Bsz * 4];
__device__ float g_c0[16 * Bsz];
__device__ float g_xbar[16 * Bsz * Ee];
__device__ float g_wpos[16 * Bsz * 4];
__device__ float g_att[2 * Bsz * DM];
__device__ float g_O [2 * Bsz * DM];
__device__ float g_enc[Bsz * Ee];
__device__ float g_Mv[4 * DM], g_cv[DM];
__device__ float g_Mc[4 * Ee], g_cc[Ee];
__device__ float g_Rk[4 * DM], g_s1[DM];
__device__ float g_Rq[4 * DM], g_sq[DM];

// ---------------------------------------------------------------------------
// WMMA bf16 split GEMM engine v5.
//   C = A @ B (+bias). CTA 64(M) x 128(N), K-chunk 32, double buffered;
//   hi/lo bf16 resident; 3 passes (hh+hl+lh) ~= fp32.
//   NT: B[n][k] row-major source. POOL: A row m = max(Asrc[2m], Asrc[2m+1]).
//   GATHER: A row r from text_table[nt[(r>>1)*Nn + (r&1)]].
//   EPI=1: C[r][c] += ec[c] + npos4(r) . eM[:,c]      (Q rank-4 epilogue)
//   EPI=2: C[r][zc] += ec[zc] + wpos4(r,z) . eM[:,zc] (att rank-4 epilogue)
// smem (bytes): Asm 4x2560 bf16 [0,20480) ; Bsm 4x5120 bf16 [20480,61440) ;
//               stage 8x256 fp32 [61440,69632)
// ---------------------------------------------------------------------------
#define ALD 40
#define BLDNN 136
#define BLDNT 40
#define A_COPY 2560
#define B_COPY 5120
#define GSMEM_BYTES 69632

template<bool NT, bool POOL, bool GATHER, int EPI>
__global__ void __launch_bounds__(256) wmma_gemm5(
        const float* __restrict__ A0, int lda, long az,
        const float* __restrict__ B0, int ldb, long bz,
        float* __restrict__ C0, int ldc, long cz,
        const float* __restrict__ bias, int K,
        const int* __restrict__ nt,
        const float* __restrict__ ep_a,   // npos (EPI=1) or wpos (EPI=2)
        const float* __restrict__ ep_M,   // Rq or Mv   [4][DM]
        const float* __restrict__ ep_c) { // sq or cv   [DM]
    const float* A = A0 + (size_t)blockIdx.z * az;
    const float* B = B0 + (size_t)blockIdx.z * bz;
    float*       C = C0 + (size_t)blockIdx.z * cz;

    extern __shared__ char smraw[];
    __nv_bfloat16* Asm = (__nv_bfloat16*)smraw;
    __nv_bfloat16* Bsm = (__nv_bfloat16*)(smraw + 20480);
    float* stage = (float*)(smraw + 61440);

    int tid = threadIdx.x;
    int warp = tid >> 5, lane = tid & 31;
    int row0 = blockIdx.y * 64, col0 = blockIdx.x * 128;
    int wm = warp >> 2, wn = warp & 3;
    int m0 = wm * 32, n0 = wn * 32;

    int arr = tid >> 2, ak8 = (tid & 3) << 3;   // A: 4 thr/row, 8 k each
    int bkr = tid >> 3, bc = (tid & 7) << 4;    // B NN: 32 rows x 16 cols
    int bi = tid >> 1, bko = (tid & 1) << 4;    // B NT: 128 rows x 16 k

    const float *Ar0, *Ar1 = nullptr;
    if (GATHER) {
        int gr = row0 + arr;
        int id = nt[(gr >> 1) * Nn + (gr & 1)];
        Ar0 = A + (size_t)id * lda;
    } else if (POOL) {
        Ar0 = A + (size_t)(2 * (row0 + arr)) * lda;
        Ar1 = A + (size_t)(2 * (row0 + arr) + 1) * lda;
    } else {
        Ar0 = A + (size_t)(row0 + arr) * lda;
    }

    const int nk = K >> 5;

    float4 fa0, fa1, fb[4];
    auto fetch = [&](int c) {
        int kb = c << 5;
        fa0 = *(const float4*)(Ar0 + kb + ak8);
        fa1 = *(const float4*)(Ar0 + kb + ak8 + 4);
        if (POOL) {
            float4 y0 = *(const float4*)(Ar1 + kb + ak8);
            float4 y1 = *(const float4*)(Ar1 + kb + ak8 + 4);
            fa0.x = fmaxf(fa0.x, y0.x); fa0.y = fmaxf(fa0.y, y0.y);
            fa0.z = fmaxf(fa0.z, y0.z); fa0.w = fmaxf(fa0.w, y0.w);
            fa1.x = fmaxf(fa1.x, y1.x); fa1.y = fmaxf(fa1.y, y1.y);
            fa1.z = fmaxf(fa1.z, y1.z); fa1.w = fmaxf(fa1.w, y1.w);
        }
        if (NT) {
            const float* bp = B + (size_t)(col0 + bi) * ldb + kb + bko;
            #pragma unroll
            for (int q = 0; q < 4; q++) fb[q] = *(const float4*)(bp + 4 * q);
        } else {
            const float* bp = B + (size_t)(kb + bkr) * ldb + col0 + bc;
            #pragma unroll
            for (int q = 0; q < 4; q++) fb[q] = *(const float4*)(bp + 4 * q);
        }
    };
    auto commit = [&](int buf) {
        __nv_bfloat16* ah = Asm + (buf * 2 + 0) * A_COPY + arr * ALD + ak8;
        __nv_bfloat16* al = Asm + (buf * 2 + 1) * A_COPY + arr * ALD + ak8;
        #pragma unroll
        for (int u = 0; u < 4; u++) {
            float x = (&fa0.x)[u];
            __nv_bfloat16 h = __float2bfloat16(x);
            ah[u] = h; al[u] = __float2bfloat16(x - __bfloat162float(h));
            float y = (&fa1.x)[u];
            __nv_bfloat16 g = __float2bfloat16(y);
            ah[4 + u] = g; al[4 + u] = __float2bfloat16(y - __bfloat162float(g));
        }
        __nv_bfloat16 *bh, *bl;
        if (NT) {
            bh = Bsm + (buf * 2 + 0) * B_COPY + bi * BLDNT + bko;
            bl = Bsm + (buf * 2 + 1) * B_COPY + bi * BLDNT + bko;
        } else {
            bh = Bsm + (buf * 2 + 0) * B_COPY + bkr * BLDNN + bc;
            bl = Bsm + (buf * 2 + 1) * B_COPY + bkr * BLDNN + bc;
        }
        #pragma unroll
        for (int q = 0; q < 4; q++)
            #pragma unroll
            for (int u = 0; u < 4; u++) {
                float x = (&fb[q].x)[u];
                __nv_bfloat16 h = __float2bfloat16(x);
                bh[4 * q + u] = h;
                bl[4 * q + u] = __float2bfloat16(x - __bfloat162float(h));
            }
    };

    fetch(0);
    commit(0);
    __syncthreads();

    wmma::fragment<wmma::accumulator, 16, 16, 16, float> acc[2][2];
    #pragma unroll
    for (int i = 0; i < 2; i++)
        #pragma unroll
        for (int j = 0; j < 2; j++)
            wmma::fill_fragment(acc[i][j], 0.0f);

    for (int k0 = 0; k0 < nk; k0++) {
        int buf = k0 & 1;
        if (k0 + 1 < nk) fetch(k0 + 1);

        const __nv_bfloat16* aH = Asm + (buf * 2 + 0) * A_COPY;
        const __nv_bfloat16* aL = Asm + (buf * 2 + 1) * A_COPY;
        const __nv_bfloat16* bH = Bsm + (buf * 2 + 0) * B_COPY;
        const __nv_bfloat16* bL = Bsm + (buf * 2 + 1) * B_COPY;

        #pragma unroll
        for (int k2 = 0; k2 < 2; k2++) {
            int ko = k2 << 4;
            wmma::fragment<wmma::matrix_a, 16, 16, 16, __nv_bfloat16,
                           wmma::row_major> ah0, ah1, al0, al1;
            wmma::load_matrix_sync(ah0, aH + (m0 +  0) * ALD + ko, ALD);
            wmma::load_matrix_sync(ah1, aH + (m0 + 16) * ALD + ko, ALD);
            wmma::load_matrix_sync(al0, aL + (m0 +  0) * ALD + ko, ALD);
            wmma::load_matrix_sync(al1, aL + (m0 + 16) * ALD + ko, ALD);
            if (NT) {
                wmma::fragment<wmma::matrix_b, 16, 16, 16, __nv_bfloat16,
                               wmma::col_major> bh0, bh1, bl0, bl1;
                wmma::load_matrix_sync(bh0, bH + (n0 +  0) * BLDNT + ko, BLDNT);
                wmma::load_matrix_sync(bh1, bH + (n0 + 16) * BLDNT + ko, BLDNT);
                wmma::load_matrix_sync(bl0, bL + (n0 +  0) * BLDNT + ko, BLDNT);
                wmma::load_matrix_sync(bl1, bL + (n0 + 16) * BLDNT + ko, BLDNT);
                wmma::mma_sync(acc[0][0], ah0, bh0, acc[0][0]);
                wmma::mma_sync(acc[0][1], ah0, bh1, acc[0][1]);
                wmma::mma_sync(acc[1][0], ah1, bh0, acc[1][0]);
                wmma::mma_sync(acc[1][1], ah1, bh1, acc[1][1]);
                wmma::mma_sync(acc[0][0], ah0, bl0, acc[0][0]);
                wmma::mma_sync(acc[0][1], ah0, bl1, acc[0][1]);
                wmma::mma_sync(acc[1][0], ah1, bl0, acc[1][0]);
                wmma::mma_sync(acc[1][1], ah1, bl1, acc[1][1]);
                wmma::mma_sync(acc[0][0], al0, bh0, acc[0][0]);
                wmma::mma_sync(acc[0][1], al0, bh1, acc[0][1]);
                wmma::mma_sync(acc[1][0], al1, bh0, acc[1][0]);
                wmma::mma_sync(acc[1][1], al1, bh1, acc[1][1]);
            } else {
                wmma::fragment<wmma::matrix_b, 16, 16, 16, __nv_bfloat16,
                               wmma::row_major> bh0, bh1, bl0, bl1;
                wmma::load_matrix_sync(bh0, bH + ko * BLDNN + n0, BLDNN);
                wmma::load_matrix_sync(bh1, bH + ko * BLDNN + n0 + 16, BLDNN);
                wmma::load_matrix_sync(bl0, bL + ko * BLDNN + n0, BLDNN);
                wmma::load_matrix_sync(bl1, bL + ko * BLDNN + n0 + 16, BLDNN);
                wmma::mma_sync(acc[0][0], ah0, bh0, acc[0][0]);
                wmma::mma_sync(acc[0][1], ah0, bh1, acc[0][1]);
                wmma::mma_sync(acc[1][0], ah1, bh0, acc[1][0]);
                wmma::mma_sync(acc[1][1], ah1, bh1, acc[1][1]);
                wmma::mma_sync(acc[0][0], ah0, bl0, acc[0][0]);
                wmma::mma_sync(acc[0][1], ah0, bl1, acc[0][1]);
                wmma::mma_sync(acc[1][0], ah1, bl0, acc[1][0]);
                wmma::mma_sync(acc[1][1], ah1, bl1, acc[1][1]);
                wmma::mma_sync(acc[0][0], al0, bh0, acc[0][0]);
                wmma::mma_sync(acc[0][1], al0, bh1, acc[0][1]);
                wmma::mma_sync(acc[1][0], al1, bh0, acc[1][0]);
                wmma::mma_sync(acc[1][1], al1, bh1, acc[1][1]);
            }
        }
        if (k0 + 1 < nk) commit(buf ^ 1);
        __syncthreads();
    }

    // epilogue: stage each 16x16 frag; each lane writes two float4s of row rr.
    float* st = &stage[warp * 256];
    int rr = lane >> 1, cc = (lane & 1) << 3;
    #pragma unroll
    for (int i = 0; i < 2; i++)
        #pragma unroll
        for (int j = 0; j < 2; j++) {
            wmma::store_matrix_sync(st, acc[i][j], 16, wmma::mem_row_major);
            __syncwarp();
            int gr = row0 + m0 + 16 * i + rr;
            int gc = col0 + n0 + 16 * j + cc;
            float4 v0 = *(float4*)&st[rr * 16 + cc];
            float4 v1 = *(float4*)&st[rr * 16 + cc + 4];
            if (bias) {
                const float* bp = bias + gc;
                v0.x += bp[0]; v0.y += bp[1]; v0.z += bp[2]; v0.w += bp[3];
                v1.x += bp[4]; v1.y += bp[5]; v1.z += bp[6]; v1.w += bp[7];
            }
            if (EPI) {
                float4 p;
                int gcol = gc;
                if (EPI == 1) {
                    p = *(const float4*)(ep_a + (size_t)((gr >> 1) * Nn + (gr & 1)) * 4);
                } else {
                    p = *(const float4*)(ep_a + ((size_t)gr * 8 + blockIdx.z) * 4);
                    gcol = gc + (int)blockIdx.z * 128;
                }
                #pragma unroll
                for (int u = 0; u < 4; u++) {
                    int c0i = gcol + u;
                    (&v0.x)[u] += ep_c[c0i] + p.x * ep_M[c0i] + p.y * ep_M[DM + c0i]
                                + p.z * ep_M[2 * DM + c0i] + p.w * ep_M[3 * DM + c0i];
                    int c1i = gcol + 4 + u;
                    (&v1.x)[u] += ep_c[c1i] + p.x * ep_M[c1i] + p.y * ep_M[DM + c1i]
                                + p.z * ep_M[2 * DM + c1i] + p.w * ep_M[3 * DM + c1i];
                }
            }
            *(float4*)(C + (size_t)gr * ldc + gc) = v0;
            *(float4*)(C + (size_t)gr * ldc + gc + 4) = v1;
            __syncwarp();
        }
}

// ---------------------------------------------------------------------------
// Rank-4 folds: init + ONE merged split-K kernel (z selects config).
// ---------------------------------------------------------------------------
__global__ void fold_init(float* __restrict__ Mv, float* __restrict__ cv,
                          const float* __restrict__ bv,
                          float* __restrict__ Rk, float* __restrict__ s1,
                          const float* __restrict__ bk,
                          float* __restrict__ Rq, float* __restrict__ sq,
                          const float* __restrict__ bq,
                          float* __restrict__ Mc, float* __restrict__ cc,
                          const float* __restrict__ pb) {
    int i = blockIdx.x * blockDim.x + threadIdx.x;
    if (i < 4 * DM) {
        Mv[i] = 0.f; Rk[i] = 0.f; Rq[i] = 0.f;
        if (i < 4 * Ee) Mc[i] = 0.f;
    } else {
        int j = i - 4 * DM;
        if (j < DM) {
            cv[j] = bv[j]; s1[j] = bk[j]; sq[j] = bq[j];
            if (j < Ee) cc[j] = pb[j];
        }
    }
}

#define FOLD_KSPLIT 16
__global__ void __launch_bounds__(128) fuse_all(
        const float* __restrict__ pos_W, const float* __restrict__ pos_b,
        const float* __restrict__ cand_W, const float* __restrict__ cand_b,
        const float* __restrict__ WvB, const float* __restrict__ WkB,
        const float* __restrict__ WqB, const float* __restrict__ projW,
        float* __restrict__ Mv, float* __restrict__ cv,
        float* __restrict__ Rk, float* __restrict__ s1,
        float* __restrict__ Rq, float* __restrict__ sq,
        float* __restrict__ Mc, float* __restrict__ cc) {
    int z = blockIdx.z;
    const float* W4   = (z == 3) ? cand_W : pos_W;
    const float* b_in = (z == 3) ? cand_b : pos_b;
    const float* Wbot = (z == 0) ? WvB : (z == 1) ? WkB : (z == 2) ? WqB : projW;
    float* M_out = (z == 0) ? Mv : (z == 1) ? Rk : (z == 2) ? Rq : Mc;
    float* c_out = (z == 0) ? cv : (z == 1) ? s1 : (z == 2) ? sq : cc;
    int Nout = (z == 3) ? Ee : DM;
    int ldb  = Nout;

    int n = blockIdx.x * 128 + threadIdx.x;
    if (n >= Nout) return;
    const int chunk = Ee / FOLD_KSPLIT;     // 32
    int k0 = blockIdx.y * chunk, k1 = k0 + chunk;
    float m0 = 0.f, m1 = 0.f, m2 = 0.f, m3 = 0.f, c = 0.f;
    for (int k = k0; k < k1; k++) {
        float w = Wbot[(size_t)k * ldb + n];
        m0 += W4[k] * w;
        m1 += W4[Ee + k] * w;
        m2 += W4[2 * Ee + k] * w;
        m3 += W4[3 * Ee + k] * w;
        c  += b_in[k] * w;
    }
    atomicAdd(&M_out[n], m0);
    atomicAdd(&M_out[Nout + n], m1);
    atomicAdd(&M_out[2 * Nout + n], m2);
    atomicAdd(&M_out[3 * Nout + n], m3);
    atomicAdd(&c_out[n], c);
}

// ---------------------------------------------------------------------------
__global__ void __launch_bounds__(256) score_consts2(
        const float* __restrict__ Q, const float* __restrict__ Rk,
        const float* __restrict__ s1, float* __restrict__ r4, float* __restrict__ c0) {
    int warp = threadIdx.x >> 5, lane = threadIdx.x & 31;
    int i = blockIdx.x * 8 + warp;
    int bq = i >> 3, h = i & 7;
    float4 qv = *(const float4*)(Q + (size_t)bq * DM + h * DEPTH + lane * 4);
    #pragma unroll
    for (int c = 0; c < 5; c++) {
        const float* src = (c < 4) ? (Rk + c * DM) : s1;
        float4 rv = *(const float4*)(src + h * DEPTH + lane * 4);
        float s = qv.x * rv.x + qv.y * rv.y + qv.z * rv.z + qv.w * rv.w;
        #pragma unroll
        for (int off = 16; off; off >>= 1) s += __shfl_xor_sync(0xffffffffu, s, off);
        if (lane == 0) {
            if (c < 4) r4[i * 4 + c] = s;
            else       c0[i] = s;
        }
    }
}

// ---------------------------------------------------------------------------
// Fused attention: scores (gather-dot) -> softmax -> xbar (gather-axpy).
// ---------------------------------------------------------------------------
#define ATTN_SMEM (13736 * 4)

__global__ void __launch_bounds__(256) attn_fused(
        const int* __restrict__ nt, const float* __restrict__ npos,
        const float* __restrict__ U, const float* __restrict__ r4,
        const float* __restrict__ c0, const float* __restrict__ text_table,
        float* __restrict__ xbar, float* __restrict__ wpos) {
    extern __shared__ float dyn[];
    float* sUt  = dyn;                  // [512][16]
    float* sT   = dyn + 8192;           // [100][33]
    float* sS   = dyn + 11492;          // [16][104]
    float* spos = dyn + 13156;          // [100][4]
    float* sr4  = dyn + 13556;          // [16][4]
    float* sc0  = dyn + 13620;          // [16]
    int*   sid  = (int*)(dyn + 13636);  // [100]

    int b = blockIdx.x, tid = threadIdx.x;
    int warp = tid >> 5, lane = tid & 31;

    for (int n = tid; n < Nn; n += 256) {
        int id = nt[b * Nn + n];
        sid[n] = id;
        float4 p = *(const float4*)(npos + (size_t)(b * Nn + n) * 4);
        spos[n * 4 + 0] = p.x; spos[n * 4 + 1] = p.y;
        spos[n * 4 + 2] = p.z; spos[n * 4 + 3] = p.w;
    }
    for (int idx = tid; idx < 16 * Ee; idx += 256) {
        int qh = idx >> 9, d = idx & 511;
        sUt[d * 16 + qh] = U[((size_t)b * 16 + qh) * Ee + d];
    }
    for (int idx = tid; idx < 64; idx += 256) sr4[idx] = r4[(size_t)b * 64 + idx];
    if (tid < 16) sc0[tid] = c0[(size_t)b * 16 + tid];
    __syncthreads();

    float m0 = (sid[0] == 0) ? 1.f : 0.f;
    float m1 = (sid[1] == 0) ? 1.f : 0.f;
    const float scale = 0.08838834764831845f;

    bool active = tid < 200;
    int qh0 = (tid & 7) * 2;
    int n0 = (tid >> 3) * 4;
    float acc[2][4] = {};

    for (int kc = 0; kc < 16; kc++) {
        for (int idx = tid; idx < Nn * 32; idx += 256) {
            int n = idx >> 5, d = idx & 31;
            sT[n * 33 + d] = text_table[(size_t)sid[n] * Ee + kc * 32 + d];
        }
        __syncthreads();
        if (active) {
            #pragma unroll
            for (int d = 0; d < 32; d++) {
                int gd = kc * 32 + d;
                float2 u2 = *(float2*)&sUt[gd * 16 + qh0];
                #pragma unroll
                for (int i = 0; i < 4; i++) {
                    float t = sT[(n0 + i) * 33 + d];
                    acc[0][i] += u2.x * t;
                    acc[1][i] += u2.y * t;
                }
            }
        }
        __syncthreads();
    }
    if (active) {
        #pragma unroll
        for (int j = 0; j < 2; j++) {
            int qh = qh0 + j;
            float mq = (qh < 8) ? m0 : m1;
            #pragma unroll
            for (int i = 0; i < 4; i++) {
                int n = n0 + i;
                float s = acc[j][i]
                        + spos[n * 4 + 0] * sr4[qh * 4 + 0]
                        + spos[n * 4 + 1] * sr4[qh * 4 + 1]
                        + spos[n * 4 + 2] * sr4[qh * 4 + 2]
                        + spos[n * 4 + 3] * sr4[qh * 4 + 3]
                        + sc0[qh];
                float mn = (sid[n] == 0) ? 1.f : 0.f;
                sS[qh * 104 + n] = s * scale + mq * mn * (-1e9f);
            }
        }
    }
    __syncthreads();

    for (int r = warp; r < 16; r += 8) {
        float* row = sS + r * 104;
        float mx = -1e30f;
        for (int jn = lane; jn < Nn; jn += 32) mx = fmaxf(mx, row[jn]);
        #pragma unroll
        for (int off = 16; off; off >>= 1)
            mx = fmaxf(mx, __shfl_xor_sync(0xffffffffu, mx, off));
        float ev[4]; int cnt = 0; float sum = 0.f;
        for (int jn = lane; jn < Nn; jn += 32) {
            float e = expf(row[jn] - mx);
            ev[cnt++] = e; sum += e;
        }
        #pragma unroll
        for (int off = 16; off; off >>= 1)
            sum += __shfl_xor_sync(0xffffffffu, sum, off);
        float inv = 1.f / sum;
        cnt = 0;
        for (int jn = lane; jn < Nn; jn += 32) row[jn] = ev[cnt++] * inv;
    }
    __syncthreads();

    if (tid < 64) {
        int qh = tid >> 2, c = tid & 3;
        float s = 0.f;
        for (int n = 0; n < Nn; n++) s += sS[qh * 104 + n] * spos[n * 4 + c];
        wpos[((size_t)b * 16 + qh) * 4 + c] = s;
    }

    // ---- phase C: xbar via float4 smem loads (4x fewer LDS) ----
    float* sT2 = dyn;                   // reuse [16][512]
    int qh = tid & 15, dg = tid >> 4;   // dg in 0..15; d = dg*4 + 64*j + u
    float xa[32] = {};
    for (int nc = 0; nc < 7; nc++) {
        __syncthreads();
        for (int idx = tid; idx < 16 * Ee; idx += 256) {
            int rr = idx >> 9, d = idx & 511;
            int n = nc * 16 + rr;
            if (n < Nn) sT2[rr * Ee + d] = text_table[(size_t)sid[n] * Ee + d];
        }
        __syncthreads();
        int nmax = min(16, Nn - nc * 16);
        for (int rr = 0; rr < nmax; rr++) {
            float w = sS[qh * 104 + nc * 16 + rr];
            const float4* tp = (const float4*)(sT2 + rr * Ee) + dg;
            #pragma unroll
            for (int j = 0; j < 8; j++) {
                float4 t4 = tp[16 * j];
                xa[4 * j + 0] += w * t4.x;
                xa[4 * j + 1] += w * t4.y;
                xa[4 * j + 2] += w * t4.z;
                xa[4 * j + 3] += w * t4.w;
            }
        }
    }
    __syncthreads();
    float* sX = dyn;
    #pragma unroll
    for (int j = 0; j < 8; j++)
        *(float4*)&sX[qh * Ee + dg * 4 + 64 * j] =
            make_float4(xa[4 * j], xa[4 * j + 1], xa[4 * j + 2], xa[4 * j + 3]);
    __syncthreads();
    for (int idx = tid; idx < 16 * Ee; idx += 256) {
        int q2 = idx >> 9, d = idx & 511;
        xbar[((size_t)b * 16 + q2) * Ee + d] = sX[idx];
    }
}

// ---------------------------------------------------------------------------
__global__ void __launch_bounds__(128) cosine_kernel(
        const float* __restrict__ enc, const float* __restrict__ cand_pos,
        const float* __restrict__ Mc, const int* __restrict__ field_id,
        const float* __restrict__ field_table, float* __restrict__ out) {
    __shared__ float red[3][4];
    int b = blockIdx.x, t = threadIdx.x;
    int warp = t >> 5, lane = t & 31;
    const float* fp = field_table + (size_t)field_id[b] * Ee;
    float4 cp = *(const float4*)(cand_pos + (size_t)b * 4);
    float na = 0.f, nb = 0.f, dp = 0.f;
    for (int j = t; j < Ee; j += 128) {
        float e = enc[(size_t)b * Ee + j]
                + cp.x * Mc[j] + cp.y * Mc[Ee + j]
                + cp.z * Mc[2 * Ee + j] + cp.w * Mc[3 * Ee + j];
        float f = fp[j];
        na += e * e; nb += f * f; dp += e * f;
    }
    #pragma unroll
    for (int off = 16; off; off >>= 1) {
        na += __shfl_xor_sync(0xffffffffu, na, off);
        nb += __shfl_xor_sync(0xffffffffu, nb, off);
        dp += __shfl_xor_sync(0xffffffffu, dp, off);
    }
    if (lane == 0) { red[0][warp] = na; red[1][warp] = nb; red[2][warp] = dp; }
    __syncthreads();
    if (t == 0) {
        na = red[0][0] + red[0][1] + red[0][2] + red[0][3];
        nb = red[1][0] + red[1][1] + red[1][2] + red[1][3];
        dp = red[2][0] + red[2][1] + red[2][2] + red[2][3];
        out[b] = -dp * rsqrtf(fmaxf(na, 1e-12f)) * rsqrtf(fmaxf(nb, 1e-12f));
    }
}

// ---------------------------------------------------------------------------
extern "C" void kernel_launch(void* const* d_in, const int* in_sizes, int n_in,
                              void* d_out, int out_size) {
    const int*   field_id   = (const int*)  d_in[0];
    const float* cand_pos   = (const float*)d_in[1];
    const int*   nt         = (const int*)  d_in[2];
    const float* npos       = (const float*)d_in[3];
    const float* text_table = (const float*)d_in[4];
    const float* field_tab  = (const float*)d_in[5];
    const float* cand_W     = (const float*)d_in[6];
    const float* cand_b     = (const float*)d_in[7];
    const float* pos_W      = (const float*)d_in[8];
    const float* pos_b      = (const float*)d_in[9];
    const float* Wq         = (const float*)d_in[10];
    const float* bq         = (const float*)d_in[11];
    const float* Wk         = (const float*)d_in[12];
    const float* bk         = (const float*)d_in[13];
    const float* Wv         = (const float*)d_in[14];
    const float* bv         = (const float*)d_in[15];
    const float* Wo         = (const float*)d_in[16];
    const float* bo         = (const float*)d_in[17];
    const float* proj_W     = (const float*)d_in[18];
    const float* proj_b     = (const float*)d_in[19];
    float* out = (float*)d_out;

    float *Qb, *Ub, *r4b, *c0b, *xbarb, *wposb, *attb, *Ob, *encb;
    float *Mvp, *cvp, *Mcp, *ccp, *Rkp, *s1p, *Rqp, *sqp;
    cudaGetSymbolAddress((void**)&Qb,    g_Q);
    cudaGetSymbolAddress((void**)&Ub,    g_U);
    cudaGetSymbolAddress((void**)&r4b,   g_r4);
    cudaGetSymbolAddress((void**)&c0b,   g_c0);
    cudaGetSymbolAddress((void**)&xbarb, g_xbar);
    cudaGetSymbolAddress((void**)&wposb, g_wpos);
    cudaGetSymbolAddress((void**)&attb,  g_att);
    cudaGetSymbolAddress((void**)&Ob,    g_O);
    cudaGetSymbolAddress((void**)&encb,  g_enc);
    cudaGetSymbolAddress((void**)&Mvp,   g_Mv);
    cudaGetSymbolAddress((void**)&cvp,   g_cv);
    cudaGetSymbolAddress((void**)&Mcp,   g_Mc);
    cudaGetSymbolAddress((void**)&ccp,   g_cc);
    cudaGetSymbolAddress((void**)&Rkp,   g_Rk);
    cudaGetSymbolAddress((void**)&s1p,   g_s1);
    cudaGetSymbolAddress((void**)&Rqp,   g_Rq);
    cudaGetSymbolAddress((void**)&sqp,   g_sq);

    cudaFuncSetAttribute(attn_fused,
                         cudaFuncAttributeMaxDynamicSharedMemorySize, ATTN_SMEM);
    cudaFuncSetAttribute(wmma_gemm5<false, false, false, 0>,
                         cudaFuncAttributeMaxDynamicSharedMemorySize, GSMEM_BYTES);
    cudaFuncSetAttribute(wmma_gemm5<true, false, false, 0>,
                         cudaFuncAttributeMaxDynamicSharedMemorySize, GSMEM_BYTES);
    cudaFuncSetAttribute(wmma_gemm5<false, true, false, 0>,
                         cudaFuncAttributeMaxDynamicSharedMemorySize, GSMEM_BYTES);
    cudaFuncSetAttribute(wmma_gemm5<false, false, true, 1>,
                         cudaFuncAttributeMaxDynamicSharedMemorySize, GSMEM_BYTES);
    cudaFuncSetAttribute(wmma_gemm5<false, false, false, 2>,
                         cudaFuncAttributeMaxDynamicSharedMemorySize, GSMEM_BYTES);

    // ---- rank-4 folds: init + ONE merged split-K launch ----
    fold_init<<<(5 * DM + 255) / 256, 256>>>(Mvp, cvp, bv, Rkp, s1p, bk,
                                             Rqp, sqp, bq, Mcp, ccp, proj_b);
    fuse_all<<<dim3(DM / 128, FOLD_KSPLIT, 4), 128>>>(
        pos_W, pos_b, cand_W, cand_b,
        Wv + (size_t)Ee * DM, Wk + (size_t)Ee * DM, Wq + (size_t)Ee * DM, proj_W,
        Mvp, cvp, Rkp, s1p, Rqp, sqp, Mcp, ccp);

    // Q = gather(text_table) @ Wq_top + (npos@Rq + sq)   [gather+epi fused]
    wmma_gemm5<false, false, true, 1><<<dim3(8, 16, 1), 256, GSMEM_BYTES>>>(
        text_table, Ee, 0, Wq, DM, 0, Qb, DM, 0, nullptr, Ee, nt,
        npos, Rqp, sqp);

    // U_top = q_h @ Wk_top_h^T  (8 x [1024 x 512 x 128] NT)
    wmma_gemm5<true, false, false, 0><<<dim3(4, 16, 8), 256, GSMEM_BYTES>>>(
        Qb, DM, 128, Wk, DM, 128, Ub, 8 * Ee, Ee, nullptr, DEPTH, nullptr,
        nullptr, nullptr, nullptr);

    // per-(bq,h) score constants
    score_consts2<<<16 * Bsz / 8, 256>>>(Qb, Rkp, s1p, r4b, c0b);

    // fused gather-scores -> softmax -> xbar/wpos
    attn_fused<<<Bsz, 256, ATTN_SMEM>>>(nt, npos, Ub, r4b, c0b, text_table,
                                        xbarb, wposb);

    // att = xbar @ Wv_top + (wpos@Mv + cv)   [epi fused]
    wmma_gemm5<false, false, false, 2><<<dim3(1, 16, 8), 256, GSMEM_BYTES>>>(
        xbarb, 8 * Ee, Ee, Wv, DM, 128, attb, DM, 128, nullptr, Ee, nullptr,
        wposb, Mvp, cvp);

    // O = att @ Wo + bo  (1024 x 1024 x 1024)
    wmma_gemm5<false, false, false, 0><<<dim3(8, 16, 1), 256, GSMEM_BYTES>>>(
        attb, DM, 0, Wo, DM, 0, Ob, DM, 0, bo, DM, nullptr,
        nullptr, nullptr, nullptr);

    // enc = max-pool(O rows) @ proj_W[512:,:] + cc  (pool fused)
    wmma_gemm5<false, true, false, 0><<<dim3(4, 8, 1), 256, GSMEM_BYTES>>>(
        Ob, DM, 0, proj_W + (size_t)Ee * Ee, Ee, 0, encb, Ee, 0, ccp, DM, nullptr,
        nullptr, nullptr, nullptr);

    // cosine loss
    cosine_kernel<<<Bsz, 128>>>(encb, cand_pos, Mcp, field_id, field_tab, out);
}

// round 17
// speedup vs baseline: 1.0334x; 1.0334x over previous
#include <cuda_runtime.h>
#include <cuda_bf16.h>
#include <mma.h>
#include <cstdint>

using namespace nvcuda;

// ---------------------------------------------------------------------------
// Model_57183194578962 — fused neighbor-attention + cosine loss
// B=512, N=100, E=512, D_MODEL=1024, H=8, DEPTH=128, VOCAB=50000
//
// Round 16: revert round-15 (regression); engine v6 — 128 threads, warp tile
// 32x64 (2x MMAs per fragment load; engine was measured L1/smem-bound).
// ---------------------------------------------------------------------------

#define Bsz 512
#define Nn  100
#define Ee  512
#define DM  1024
#define Hh  8
#define DEPTH 128

// ------------------------- static scratch ----------------------------------
__device__ float g_Q [2 * Bsz * DM];
__device__ float g_U [16 * Bsz * Ee];
__device__ float g_r4[16 * Bsz * 4];
__device__ float g_c0[16 * Bsz];
__device__ float g_xbar[16 * Bsz * Ee];
__device__ float g_wpos[16 * Bsz * 4];
__device__ float g_att[2 * Bsz * DM];
__device__ float g_O [2 * Bsz * DM];
__device__ float g_enc[Bsz * Ee];
__device__ float g_Mv[4 * DM], g_cv[DM];
__device__ float g_Mc[4 * Ee], g_cc[Ee];
__device__ float g_Rk[4 * DM], g_s1[DM];
__device__ float g_Rq[4 * DM], g_sq[DM];

// ---------------------------------------------------------------------------
// WMMA bf16 split GEMM engine v6.
//   C = A @ B (+bias). CTA tile 64(M) x 128(N), K-chunk 32 (2 x k16),
//   double buffered; hi/lo bf16 resident; 3 passes (hh+hl+lh) ~= fp32.
//   128 threads = 4 warps as 2(M) x 2(N); warp tile 32x64:
//   per k16 substep 12 fragment loads -> 24 MMAs (2x density of v4).
//   NT: B[n][k] row-major source. POOL: A row m = max(Asrc[2m], Asrc[2m+1]).
//   GATHER: A row r from text_table[nt[(r>>1)*Nn + (r&1)]].
// smem (bytes): Asm 4x2560 bf16 [0,20480) ; Bsm 4x5120 bf16 [20480,61440) ;
//               stage 4 warps x 256 fp32 [61440,65536)
// ---------------------------------------------------------------------------
#define ALD 40
#define BLDNN 136
#define BLDNT 40
#define A_COPY 2560
#define B_COPY 5120
#define GSMEM_BYTES 65536

template<bool NT, bool POOL, bool GATHER>
__global__ void __launch_bounds__(128) wmma_gemm6(
        const float* __restrict__ A0, int lda, long az,
        const float* __restrict__ B0, int ldb, long bz,
        float* __restrict__ C0, int ldc, long cz,
        const float* __restrict__ bias, int K,
        const int* __restrict__ nt) {
    const float* A = A0 + (size_t)blockIdx.z * az;
    const float* B = B0 + (size_t)blockIdx.z * bz;
    float*       C = C0 + (size_t)blockIdx.z * cz;

    extern __shared__ char smraw[];
    __nv_bfloat16* Asm = (__nv_bfloat16*)smraw;
    __nv_bfloat16* Bsm = (__nv_bfloat16*)(smraw + 20480);
    float* stage = (float*)(smraw + 61440);

    int tid = threadIdx.x;
    int warp = tid >> 5, lane = tid & 31;
    int row0 = blockIdx.y * 64, col0 = blockIdx.x * 128;
    int wm = warp >> 1, wn = warp & 1;
    int m0 = wm * 32, n0 = wn * 64;

    // A: 2 threads/row, 16 k each (4 float4)
    int arr = tid >> 1, ak = (tid & 1) << 4;
    // B NN: 32 k-rows x 128 cols; 4 threads/row, 32 cols each (8 float4)
    int bkr = tid >> 2, bc = (tid & 3) << 5;
    // B NT: 128 n-rows x 32 k; 1 thread/row (8 float4)
    int bi = tid;

    const float *Ar0, *Ar1 = nullptr;
    if (GATHER) {
        int gr = row0 + arr;
        int id = nt[(gr >> 1) * Nn + (gr & 1)];
        Ar0 = A + (size_t)id * lda;
    } else if (POOL) {
        Ar0 = A + (size_t)(2 * (row0 + arr)) * lda;
        Ar1 = A + (size_t)(2 * (row0 + arr) + 1) * lda;
    } else {
        Ar0 = A + (size_t)(row0 + arr) * lda;
    }

    const int nk = K >> 5;

    float4 fa[4], fb[8];
    auto fetch = [&](int c) {
        int kb = c << 5;
        #pragma unroll
        for (int q = 0; q < 4; q++)
            fa[q] = *(const float4*)(Ar0 + kb + ak + 4 * q);
        if (POOL) {
            #pragma unroll
            for (int q = 0; q < 4; q++) {
                float4 y = *(const float4*)(Ar1 + kb + ak + 4 * q);
                fa[q].x = fmaxf(fa[q].x, y.x); fa[q].y = fmaxf(fa[q].y, y.y);
                fa[q].z = fmaxf(fa[q].z, y.z); fa[q].w = fmaxf(fa[q].w, y.w);
            }
        }
        if (NT) {
            const float* bp = B + (size_t)(col0 + bi) * ldb + kb;
            #pragma unroll
            for (int q = 0; q < 8; q++) fb[q] = *(const float4*)(bp + 4 * q);
        } else {
            const float* bp = B + (size_t)(kb + bkr) * ldb + col0 + bc;
            #pragma unroll
            for (int q = 0; q < 8; q++) fb[q] = *(const float4*)(bp + 4 * q);
        }
    };
    auto commit = [&](int buf) {
        __nv_bfloat16* ah = Asm + (buf * 2 + 0) * A_COPY + arr * ALD + ak;
        __nv_bfloat16* al = Asm + (buf * 2 + 1) * A_COPY + arr * ALD + ak;
        #pragma unroll
        for (int q = 0; q < 4; q++)
            #pragma unroll
            for (int u = 0; u < 4; u++) {
                float x = (&fa[q].x)[u];
                __nv_bfloat16 h = __float2bfloat16(x);
                ah[4 * q + u] = h;
                al[4 * q + u] = __float2bfloat16(x - __bfloat162float(h));
            }
        __nv_bfloat16 *bh, *bl;
        if (NT) {
            bh = Bsm + (buf * 2 + 0) * B_COPY + bi * BLDNT;
            bl = Bsm + (buf * 2 + 1) * B_COPY + bi * BLDNT;
        } else {
            bh = Bsm + (buf * 2 + 0) * B_COPY + bkr * BLDNN + bc;
            bl = Bsm + (buf * 2 + 1) * B_COPY + bkr * BLDNN + bc;
        }
        #pragma unroll
        for (int q = 0; q < 8; q++)
            #pragma unroll
            for (int u = 0; u < 4; u++) {
                float x = (&fb[q].x)[u];
                __nv_bfloat16 h = __float2bfloat16(x);
                bh[4 * q + u] = h;
                bl[4 * q + u] = __float2bfloat16(x - __bfloat162float(h));
            }
    };

    fetch(0);
    commit(0);
    __syncthreads();

    wmma::fragment<wmma::accumulator, 16, 16, 16, float> acc[2][4];
    #pragma unroll
    for (int i = 0; i < 2; i++)
        #pragma unroll
        for (int j = 0; j < 4; j++)
            wmma::fill_fragment(acc[i][j], 0.0f);

    for (int k0 = 0; k0 < nk; k0++) {
        int buf = k0 & 1;
        if (k0 + 1 < nk) fetch(k0 + 1);

        const __nv_bfloat16* aH = Asm + (buf * 2 + 0) * A_COPY;
        const __nv_bfloat16* aL = Asm + (buf * 2 + 1) * A_COPY;
        const __nv_bfloat16* bH = Bsm + (buf * 2 + 0) * B_COPY;
        const __nv_bfloat16* bL = Bsm + (buf * 2 + 1) * B_COPY;

        #pragma unroll
        for (int k2 = 0; k2 < 2; k2++) {
            int ko = k2 << 4;
            wmma::fragment<wmma::matrix_a, 16, 16, 16, __nv_bfloat16,
                           wmma::row_major> ah0, ah1, al0, al1;
            wmma::load_matrix_sync(ah0, aH + (m0 +  0) * ALD + ko, ALD);
            wmma::load_matrix_sync(ah1, aH + (m0 + 16) * ALD + ko, ALD);
            wmma::load_matrix_sync(al0, aL + (m0 +  0) * ALD + ko, ALD);
            wmma::load_matrix_sync(al1, aL + (m0 + 16) * ALD + ko, ALD);
            if (NT) {
                wmma::fragment<wmma::matrix_b, 16, 16, 16, __nv_bfloat16,
                               wmma::col_major> bh[4], bl[4];
                #pragma unroll
                for (int t = 0; t < 4; t++) {
                    wmma::load_matrix_sync(bh[t], bH + (n0 + 16 * t) * BLDNT + ko, BLDNT);
                    wmma::load_matrix_sync(bl[t], bL + (n0 + 16 * t) * BLDNT + ko, BLDNT);
                }
                #pragma unroll
                for (int t = 0; t < 4; t++) {
                    wmma::mma_sync(acc[0][t], ah0, bh[t], acc[0][t]);
                    wmma::mma_sync(acc[1][t], ah1, bh[t], acc[1][t]);
                    wmma::mma_sync(acc[0][t], ah0, bl[t], acc[0][t]);
                    wmma::mma_sync(acc[1][t], ah1, bl[t], acc[1][t]);
                    wmma::mma_sync(acc[0][t], al0, bh[t], acc[0][t]);
                    wmma::mma_sync(acc[1][t], al1, bh[t], acc[1][t]);
                }
            } else {
                wmma::fragment<wmma::matrix_b, 16, 16, 16, __nv_bfloat16,
                               wmma::row_major> bh[4], bl[4];
                #pragma unroll
                for (int t = 0; t < 4; t++) {
                    wmma::load_matrix_sync(bh[t], bH + ko * BLDNN + n0 + 16 * t, BLDNN);
                    wmma::load_matrix_sync(bl[t], bL + ko * BLDNN + n0 + 16 * t, BLDNN);
                }
                #pragma unroll
                for (int t = 0; t < 4; t++) {
                    wmma::mma_sync(acc[0][t], ah0, bh[t], acc[0][t]);
                    wmma::mma_sync(acc[1][t], ah1, bh[t], acc[1][t]);
                    wmma::mma_sync(acc[0][t], ah0, bl[t], acc[0][t]);
                    wmma::mma_sync(acc[1][t], ah1, bl[t], acc[1][t]);
                    wmma::mma_sync(acc[0][t], al0, bh[t], acc[0][t]);
                    wmma::mma_sync(acc[1][t], al1, bh[t], acc[1][t]);
                }
            }
        }
        if (k0 + 1 < nk) commit(buf ^ 1);
        __syncthreads();
    }

    // epilogue: stage each 16x16 frag; each lane writes two float4s of row rr.
    float* st = &stage[warp * 256];
    int rr = lane >> 1, cc = (lane & 1) << 3;
    #pragma unroll
    for (int i = 0; i < 2; i++)
        #pragma unroll
        for (int j = 0; j < 4; j++) {
            wmma::store_matrix_sync(st, acc[i][j], 16, wmma::mem_row_major);
            __syncwarp();
            int gr = row0 + m0 + 16 * i + rr;
            int gc = col0 + n0 + 16 * j + cc;
            float4 v0 = *(float4*)&st[rr * 16 + cc];
            float4 v1 = *(float4*)&st[rr * 16 + cc + 4];
            if (bias) {
                const float* bp = bias + gc;
                v0.x += bp[0]; v0.y += bp[1]; v0.z += bp[2]; v0.w += bp[3];
                v1.x += bp[4]; v1.y += bp[5]; v1.z += bp[6]; v1.w += bp[7];
            }
            *(float4*)(C + (size_t)gr * ldc + gc) = v0;
            *(float4*)(C + (size_t)gr * ldc + gc + 4) = v1;
            __syncwarp();
        }
}

// ---------------------------------------------------------------------------
// Rank-4 folds: init + ONE merged split-K kernel (z selects config).
// ---------------------------------------------------------------------------
__global__ void fold_init(float* __restrict__ Mv, float* __restrict__ cv,
                          const float* __restrict__ bv,
                          float* __restrict__ Rk, float* __restrict__ s1,
                          const float* __restrict__ bk,
                          float* __restrict__ Rq, float* __restrict__ sq,
                          const float* __restrict__ bq,
                          float* __restrict__ Mc, float* __restrict__ cc,
                          const float* __restrict__ pb) {
    int i = blockIdx.x * blockDim.x + threadIdx.x;
    if (i < 4 * DM) {
        Mv[i] = 0.f; Rk[i] = 0.f; Rq[i] = 0.f;
        if (i < 4 * Ee) Mc[i] = 0.f;
    } else {
        int j = i - 4 * DM;
        if (j < DM) {
            cv[j] = bv[j]; s1[j] = bk[j]; sq[j] = bq[j];
            if (j < Ee) cc[j] = pb[j];
        }
    }
}

#define FOLD_KSPLIT 16
__global__ void __launch_bounds__(128) fuse_all(
        const float* __restrict__ pos_W, const float* __restrict__ pos_b,
        const float* __restrict__ cand_W, const float* __restrict__ cand_b,
        const float* __restrict__ WvB, const float* __restrict__ WkB,
        const float* __restrict__ WqB, const float* __restrict__ projW,
        float* __restrict__ Mv, float* __restrict__ cv,
        float* __restrict__ Rk, float* __restrict__ s1,
        float* __restrict__ Rq, float* __restrict__ sq,
        float* __restrict__ Mc, float* __restrict__ cc) {
    int z = blockIdx.z;
    const float* W4   = (z == 3) ? cand_W : pos_W;
    const float* b_in = (z == 3) ? cand_b : pos_b;
    const float* Wbot = (z == 0) ? WvB : (z == 1) ? WkB : (z == 2) ? WqB : projW;
    float* M_out = (z == 0) ? Mv : (z == 1) ? Rk : (z == 2) ? Rq : Mc;
    float* c_out = (z == 0) ? cv : (z == 1) ? s1 : (z == 2) ? sq : cc;
    int Nout = (z == 3) ? Ee : DM;
    int ldb  = Nout;

    int n = blockIdx.x * 128 + threadIdx.x;
    if (n >= Nout) return;
    const int chunk = Ee / FOLD_KSPLIT;     // 32
    int k0 = blockIdx.y * chunk, k1 = k0 + chunk;
    float m0 = 0.f, m1 = 0.f, m2 = 0.f, m3 = 0.f, c = 0.f;
    for (int k = k0; k < k1; k++) {
        float w = Wbot[(size_t)k * ldb + n];
        m0 += W4[k] * w;
        m1 += W4[Ee + k] * w;
        m2 += W4[2 * Ee + k] * w;
        m3 += W4[3 * Ee + k] * w;
        c  += b_in[k] * w;
    }
    atomicAdd(&M_out[n], m0);
    atomicAdd(&M_out[Nout + n], m1);
    atomicAdd(&M_out[2 * Nout + n], m2);
    atomicAdd(&M_out[3 * Nout + n], m3);
    atomicAdd(&c_out[n], c);
}

// ---------------------------------------------------------------------------
__global__ void q_post(float* __restrict__ Q, const int* dummy,
                       const float* __restrict__ npos,
                       const float* __restrict__ Rq, const float* __restrict__ sq) {
    int idx = blockIdx.x * blockDim.x + threadIdx.x;
    if (idx >= 2 * Bsz * DM / 4) return;
    int r = idx >> 8;
    int c4 = (idx & 255) * 4;
    int b = r >> 1, i = r & 1;
    float4 p = *(const float4*)(npos + (size_t)(b * Nn + i) * 4);
    float4 v = *(float4*)(Q + (size_t)r * DM + c4);
    #pragma unroll
    for (int u = 0; u < 4; u++) {
        int c = c4 + u;
        (&v.x)[u] += sq[c] + p.x * Rq[c] + p.y * Rq[DM + c]
                   + p.z * Rq[2 * DM + c] + p.w * Rq[3 * DM + c];
    }
    *(float4*)(Q + (size_t)r * DM + c4) = v;
}

// ---------------------------------------------------------------------------
__global__ void __launch_bounds__(256) score_consts2(
        const float* __restrict__ Q, const float* __restrict__ Rk,
        const float* __restrict__ s1, float* __restrict__ r4, float* __restrict__ c0) {
    int warp = threadIdx.x >> 5, lane = threadIdx.x & 31;
    int i = blockIdx.x * 8 + warp;
    int bq = i >> 3, h = i & 7;
    float4 qv = *(const float4*)(Q + (size_t)bq * DM + h * DEPTH + lane * 4);
    #pragma unroll
    for (int c = 0; c < 5; c++) {
        const float* src = (c < 4) ? (Rk + c * DM) : s1;
        float4 rv = *(const float4*)(src + h * DEPTH + lane * 4);
        float s = qv.x * rv.x + qv.y * rv.y + qv.z * rv.z + qv.w * rv.w;
        #pragma unroll
        for (int off = 16; off; off >>= 1) s += __shfl_xor_sync(0xffffffffu, s, off);
        if (lane == 0) {
            if (c < 4) r4[i * 4 + c] = s;
            else       c0[i] = s;
        }
    }
}

// ---------------------------------------------------------------------------
// Fused attention: scores (gather-dot) -> softmax -> xbar (gather-axpy).
// ---------------------------------------------------------------------------
#define ATTN_SMEM (13736 * 4)

__global__ void __launch_bounds__(256) attn_fused(
        const int* __restrict__ nt, const float* __restrict__ npos,
        const float* __restrict__ U, const float* __restrict__ r4,
        const float* __restrict__ c0, const float* __restrict__ text_table,
        float* __restrict__ xbar, float* __restrict__ wpos) {
    extern __shared__ float dyn[];
    float* sUt  = dyn;                  // [512][16]
    float* sT   = dyn + 8192;           // [100][33]
    float* sS   = dyn + 11492;          // [16][104]
    float* spos = dyn + 13156;          // [100][4]
    float* sr4  = dyn + 13556;          // [16][4]
    float* sc0  = dyn + 13620;          // [16]
    int*   sid  = (int*)(dyn + 13636);  // [100]

    int b = blockIdx.x, tid = threadIdx.x;
    int warp = tid >> 5, lane = tid & 31;

    for (int n = tid; n < Nn; n += 256) {
        int id = nt[b * Nn + n];
        sid[n] = id;
        float4 p = *(const float4*)(npos + (size_t)(b * Nn + n) * 4);
        spos[n * 4 + 0] = p.x; spos[n * 4 + 1] = p.y;
        spos[n * 4 + 2] = p.z; spos[n * 4 + 3] = p.w;
    }
    for (int idx = tid; idx < 16 * Ee; idx += 256) {
        int qh = idx >> 9, d = idx & 511;
        sUt[d * 16 + qh] = U[((size_t)b * 16 + qh) * Ee + d];
    }
    for (int idx = tid; idx < 64; idx += 256) sr4[idx] = r4[(size_t)b * 64 + idx];
    if (tid < 16) sc0[tid] = c0[(size_t)b * 16 + tid];
    __syncthreads();

    float m0 = (sid[0] == 0) ? 1.f : 0.f;
    float m1 = (sid[1] == 0) ? 1.f : 0.f;
    const float scale = 0.08838834764831845f;

    bool active = tid < 200;
    int qh0 = (tid & 7) * 2;
    int n0 = (tid >> 3) * 4;
    float acc[2][4] = {};

    for (int kc = 0; kc < 16; kc++) {
        for (int idx = tid; idx < Nn * 32; idx += 256) {
            int n = idx >> 5, d = idx & 31;
            sT[n * 33 + d] = text_table[(size_t)sid[n] * Ee + kc * 32 + d];
        }
        __syncthreads();
        if (active) {
            #pragma unroll
            for (int d = 0; d < 32; d++) {
                int gd = kc * 32 + d;
                float2 u2 = *(float2*)&sUt[gd * 16 + qh0];
                #pragma unroll
                for (int i = 0; i < 4; i++) {
                    float t = sT[(n0 + i) * 33 + d];
                    acc[0][i] += u2.x * t;
                    acc[1][i] += u2.y * t;
                }
            }
        }
        __syncthreads();
    }
    if (active) {
        #pragma unroll
        for (int j = 0; j < 2; j++) {
            int qh = qh0 + j;
            float mq = (qh < 8) ? m0 : m1;
            #pragma unroll
            for (int i = 0; i < 4; i++) {
                int n = n0 + i;
                float s = acc[j][i]
                        + spos[n * 4 + 0] * sr4[qh * 4 + 0]
                        + spos[n * 4 + 1] * sr4[qh * 4 + 1]
                        + spos[n * 4 + 2] * sr4[qh * 4 + 2]
                        + spos[n * 4 + 3] * sr4[qh * 4 + 3]
                        + sc0[qh];
                float mn = (sid[n] == 0) ? 1.f : 0.f;
                sS[qh * 104 + n] = s * scale + mq * mn * (-1e9f);
            }
        }
    }
    __syncthreads();

    for (int r = warp; r < 16; r += 8) {
        float* row = sS + r * 104;
        float mx = -1e30f;
        for (int jn = lane; jn < Nn; jn += 32) mx = fmaxf(mx, row[jn]);
        #pragma unroll
        for (int off = 16; off; off >>= 1)
            mx = fmaxf(mx, __shfl_xor_sync(0xffffffffu, mx, off));
        float ev[4]; int cnt = 0; float sum = 0.f;
        for (int jn = lane; jn < Nn; jn += 32) {
            float e = expf(row[jn] - mx);
            ev[cnt++] = e; sum += e;
        }
        #pragma unroll
        for (int off = 16; off; off >>= 1)
            sum += __shfl_xor_sync(0xffffffffu, sum, off);
        float inv = 1.f / sum;
        cnt = 0;
        for (int jn = lane; jn < Nn; jn += 32) row[jn] = ev[cnt++] * inv;
    }
    __syncthreads();

    if (tid < 64) {
        int qh = tid >> 2, c = tid & 3;
        float s = 0.f;
        for (int n = 0; n < Nn; n++) s += sS[qh * 104 + n] * spos[n * 4 + c];
        wpos[((size_t)b * 16 + qh) * 4 + c] = s;
    }

    float* sT2 = dyn;
    int qh = tid & 15, dg = tid >> 4;
    float xa[32] = {};
    for (int nc = 0; nc < 7; nc++) {
        __syncthreads();
        for (int idx = tid; idx < 16 * Ee; idx += 256) {
            int rr = idx >> 9, d = idx & 511;
            int n = nc * 16 + rr;
            if (n < Nn) sT2[rr * Ee + d] = text_table[(size_t)sid[n] * Ee + d];
        }
        __syncthreads();
        int nmax = min(16, Nn - nc * 16);
        for (int rr = 0; rr < nmax; rr++) {
            float w = sS[qh * 104 + nc * 16 + rr];
            const float* tp = sT2 + rr * Ee + dg;
            #pragma unroll
            for (int j = 0; j < 32; j++) xa[j] += w * tp[16 * j];
        }
    }
    __syncthreads();
    float* sX = dyn;
    #pragma unroll
    for (int j = 0; j < 32; j++) sX[qh * Ee + dg + 16 * j] = xa[j];
    __syncthreads();
    for (int idx = tid; idx < 16 * Ee; idx += 256) {
        int q2 = idx >> 9, d = idx & 511;
        xbar[((size_t)b * 16 + q2) * Ee + d] = sX[idx];
    }
}

// ---------------------------------------------------------------------------
__global__ void att_post(float* __restrict__ att, const float* __restrict__ wpos,
                         const float* __restrict__ Mv, const float* __restrict__ cv) {
    int idx = blockIdx.x * blockDim.x + threadIdx.x;
    if (idx >= 2 * Bsz * DM / 4) return;
    int r = idx >> 8;
    int c4 = (idx & 255) * 4;
    int z = c4 >> 7;
    const float* wp = wpos + ((size_t)r * 8 + z) * 4;
    float w0 = wp[0], w1 = wp[1], w2 = wp[2], w3 = wp[3];
    float4 v = *(float4*)(att + (size_t)r * DM + c4);
    #pragma unroll
    for (int u = 0; u < 4; u++) {
        int c = c4 + u;
        (&v.x)[u] += cv[c] + w0 * Mv[c] + w1 * Mv[DM + c]
                   + w2 * Mv[2 * DM + c] + w3 * Mv[3 * DM + c];
    }
    *(float4*)(att + (size_t)r * DM + c4) = v;
}

// ---------------------------------------------------------------------------
__global__ void __launch_bounds__(128) cosine_kernel(
        const float* __restrict__ enc, const float* __restrict__ cand_pos,
        const float* __restrict__ Mc, const int* __restrict__ field_id,
        const float* __restrict__ field_table, float* __restrict__ out) {
    __shared__ float red[3][4];
    int b = blockIdx.x, t = threadIdx.x;
    int warp = t >> 5, lane = t & 31;
    const float* fp = field_table + (size_t)field_id[b] * Ee;
    float4 cp = *(const float4*)(cand_pos + (size_t)b * 4);
    float na = 0.f, nb = 0.f, dp = 0.f;
    for (int j = t; j < Ee; j += 128) {
        float e = enc[(size_t)b * Ee + j]
                + cp.x * Mc[j] + cp.y * Mc[Ee + j]
                + cp.z * Mc[2 * Ee + j] + cp.w * Mc[3 * Ee + j];
        float f = fp[j];
        na += e * e; nb += f * f; dp += e * f;
    }
    #pragma unroll
    for (int off = 16; off; off >>= 1) {
        na += __shfl_xor_sync(0xffffffffu, na, off);
        nb += __shfl_xor_sync(0xffffffffu, nb, off);
        dp += __shfl_xor_sync(0xffffffffu, dp, off);
    }
    if (lane == 0) { red[0][warp] = na; red[1][warp] = nb; red[2][warp] = dp; }
    __syncthreads();
    if (t == 0) {
        na = red[0][0] + red[0][1] + red[0][2] + red[0][3];
        nb = red[1][0] + red[1][1] + red[1][2] + red[1][3];
        dp = red[2][0] + red[2][1] + red[2][2] + red[2][3];
        out[b] = -dp * rsqrtf(fmaxf(na, 1e-12f)) * rsqrtf(fmaxf(nb, 1e-12f));
    }
}

// ---------------------------------------------------------------------------
extern "C" void kernel_launch(void* const* d_in, const int* in_sizes, int n_in,
                              void* d_out, int out_size) {
    const int*   field_id   = (const int*)  d_in[0];
    const float* cand_pos   = (const float*)d_in[1];
    const int*   nt         = (const int*)  d_in[2];
    const float* npos       = (const float*)d_in[3];
    const float* text_table = (const float*)d_in[4];
    const float* field_tab  = (const float*)d_in[5];
    const float* cand_W     = (const float*)d_in[6];
    const float* cand_b     = (const float*)d_in[7];
    const float* pos_W      = (const float*)d_in[8];
    const float* pos_b      = (const float*)d_in[9];
    const float* Wq         = (const float*)d_in[10];
    const float* bq         = (const float*)d_in[11];
    const float* Wk         = (const float*)d_in[12];
    const float* bk         = (const float*)d_in[13];
    const float* Wv         = (const float*)d_in[14];
    const float* bv         = (const float*)d_in[15];
    const float* Wo         = (const float*)d_in[16];
    const float* bo         = (const float*)d_in[17];
    const float* proj_W     = (const float*)d_in[18];
    const float* proj_b     = (const float*)d_in[19];
    float* out = (float*)d_out;

    float *Qb, *Ub, *r4b, *c0b, *xbarb, *wposb, *attb, *Ob, *encb;
    float *Mvp, *cvp, *Mcp, *ccp, *Rkp, *s1p, *Rqp, *sqp;
    cudaGetSymbolAddress((void**)&Qb,    g_Q);
    cudaGetSymbolAddress((void**)&Ub,    g_U);
    cudaGetSymbolAddress((void**)&r4b,   g_r4);
    cudaGetSymbolAddress((void**)&c0b,   g_c0);
    cudaGetSymbolAddress((void**)&xbarb, g_xbar);
    cudaGetSymbolAddress((void**)&wposb, g_wpos);
    cudaGetSymbolAddress((void**)&attb,  g_att);
    cudaGetSymbolAddress((void**)&Ob,    g_O);
    cudaGetSymbolAddress((void**)&encb,  g_enc);
    cudaGetSymbolAddress((void**)&Mvp,   g_Mv);
    cudaGetSymbolAddress((void**)&cvp,   g_cv);
    cudaGetSymbolAddress((void**)&Mcp,   g_Mc);
    cudaGetSymbolAddress((void**)&ccp,   g_cc);
    cudaGetSymbolAddress((void**)&Rkp,   g_Rk);
    cudaGetSymbolAddress((void**)&s1p,   g_s1);
    cudaGetSymbolAddress((void**)&Rqp,   g_Rq);
    cudaGetSymbolAddress((void**)&sqp,   g_sq);

    cudaFuncSetAttribute(attn_fused,
                         cudaFuncAttributeMaxDynamicSharedMemorySize, ATTN_SMEM);
    cudaFuncSetAttribute(wmma_gemm6<false, false, false>,
                         cudaFuncAttributeMaxDynamicSharedMemorySize, GSMEM_BYTES);
    cudaFuncSetAttribute(wmma_gemm6<true, false, false>,
                         cudaFuncAttributeMaxDynamicSharedMemorySize, GSMEM_BYTES);
    cudaFuncSetAttribute(wmma_gemm6<false, true, false>,
                         cudaFuncAttributeMaxDynamicSharedMemorySize, GSMEM_BYTES);
    cudaFuncSetAttribute(wmma_gemm6<false, false, true>,
                         cudaFuncAttributeMaxDynamicSharedMemorySize, GSMEM_BYTES);

    // ---- rank-4 folds: init + ONE merged split-K launch ----
    fold_init<<<(5 * DM + 255) / 256, 256>>>(Mvp, cvp, bv, Rkp, s1p, bk,
                                             Rqp, sqp, bq, Mcp, ccp, proj_b);
    fuse_all<<<dim3(DM / 128, FOLD_KSPLIT, 4), 128>>>(
        pos_W, pos_b, cand_W, cand_b,
        Wv + (size_t)Ee * DM, Wk + (size_t)Ee * DM, Wq + (size_t)Ee * DM, proj_W,
        Mvp, cvp, Rkp, s1p, Rqp, sqp, Mcp, ccp);

    // Q = gather(text_table) @ Wq_top  (1024 x 1024 x 512, gather fused)
    wmma_gemm6<false, false, true><<<dim3(8, 16, 1), 128, GSMEM_BYTES>>>(
        text_table, Ee, 0, Wq, DM, 0, Qb, DM, 0, nullptr, Ee, nt);
    q_post<<<(2 * Bsz * DM / 4 + 255) / 256, 256>>>(Qb, nullptr, npos, Rqp, sqp);

    // U_top = q_h @ Wk_top_h^T  (8 x [1024 x 512 x 128] NT)
    wmma_gemm6<true, false, false><<<dim3(4, 16, 8), 128, GSMEM_BYTES>>>(
        Qb, DM, 128, Wk, DM, 128, Ub, 8 * Ee, Ee, nullptr, DEPTH, nullptr);

    // per-(bq,h) score constants
    score_consts2<<<16 * Bsz / 8, 256>>>(Qb, Rkp, s1p, r4b, c0b);

    // fused gather-scores -> softmax -> xbar/wpos
    attn_fused<<<Bsz, 256, ATTN_SMEM>>>(nt, npos, Ub, r4b, c0b, text_table,
                                        xbarb, wposb);

    // att = xbar @ Wv_top  (8 x [1024 x 128 x 512])
    wmma_gemm6<false, false, false><<<dim3(1, 16, 8), 128, GSMEM_BYTES>>>(
        xbarb, 8 * Ee, Ee, Wv, DM, 128, attb, DM, 128, nullptr, Ee, nullptr);
    att_post<<<(2 * Bsz * DM / 4 + 255) / 256, 256>>>(attb, wposb, Mvp, cvp);

    // O = att @ Wo + bo  (1024 x 1024 x 1024)
    wmma_gemm6<false, false, false><<<dim3(8, 16, 1), 128, GSMEM_BYTES>>>(
        attb, DM, 0, Wo, DM, 0, Ob, DM, 0, bo, DM, nullptr);

    // enc = max-pool(O rows) @ proj_W[512:,:] + cc  (pool fused)
    wmma_gemm6<false, true, false><<<dim3(4, 8, 1), 128, GSMEM_BYTES>>>(
        Ob, DM, 0, proj_W + (size_t)Ee * Ee, Ee, 0, encb, Ee, 0, ccp, DM, nullptr);

    // cosine loss
    cosine_kernel<<<Bsz, 128>>>(encb, cand_pos, Mcp, field_id, field_tab, out);
}